// round 10
// baseline (speedup 1.0000x reference)
#include <cuda_runtime.h>
#include <cuda_bf16.h>
#include <mma.h>
#include <math.h>
#include <stdint.h>

#define BB   64
#define TT   128
#define DD   850
#define D2   1700
#define CIN  910
#define NCC  42
#define NNER 30
#define NPOS 30
#define SD   864          // padded k stride (54*16); pads stay zero
#define NTILE 54          // 16-col tiles per half
#define NKT  54           // k16 tiles
#define PD2  1728         // padded partial width: c half at 0, h half at 864

using namespace nvcuda;

// Scratch (device globals zero-initialized; pad regions never written)
__device__ float g_combined[TT * BB * CIN];
__device__ float g_x[TT * BB * DD];
__device__ float g_xw0[TT * BB * D2];
__device__ float g_hiddens[TT * BB * DD];
__device__ float g_state[9][BB * SD];
__device__ float g_hprev[BB * SD];
__device__ __align__(256) float g_part[3][5][BB * PD2];
__device__ int   g_cnt[3][NTILE];
__device__ unsigned g_bar_cnt;
__device__ unsigned g_bar_gen;
// A splits: [src 0..8 = states, 9 = hprev][term 0..2][m*SD + k], row-major bf16
__device__ __align__(256) __nv_bfloat16 g_as[10][3][BB * SD];
// W splits, transposed for wmma col_major B: [term][((wmat*2+half)*864 + n')*SD + k]
__device__ __align__(256) __nv_bfloat16 g_wt[3][(size_t)9 * 2 * 864 * SD];

struct StepInfo { int wmat; int pred; int act; };
// act: 0 tanh, 1 relu, 2 sigmoid, 3 identity
__constant__ StepInfo c_steps[9] = {
    {0, -1, 0}, {1, 0, 2}, {2, 1, 1}, {3, 1, 1}, {4, 1, 3},
    {5, 2, 0}, {6, 5, 2}, {7, 3, 0}, {8, 5, 1},
};
// Levels: {s0},{s1},{s2,s3,s4},{s5},{s6,s7,s8}
__constant__ int c_nm[5]     = {1, 1, 3, 1, 3};
__constant__ int c_sk[5]     = {5, 5, 3, 5, 3};
__constant__ int c_sid[5][3] = {{0,0,0},{1,1,1},{2,3,4},{5,5,5},{6,7,8}};

// Sense-reversing grid barrier (all CTAs co-resident).
__device__ __forceinline__ void grid_sync() {
    __syncthreads();
    if (threadIdx.x == 0) {
        __threadfence();
        volatile unsigned* vg = &g_bar_gen;
        unsigned gen = *vg;
        if (atomicAdd(&g_bar_cnt, 1u) == gridDim.x - 1) {
            g_bar_cnt = 0;
            __threadfence();
            atomicExch(&g_bar_gen, gen + 1u);
        } else {
            while (*vg == gen) { __nanosleep(64); }
        }
        __threadfence();
    }
    __syncthreads();
}

// Exact 3-way bf16 split: x == b1 + b2 + b3 (up to ~2^-26 tail).
__device__ __forceinline__ void split3(float x, __nv_bfloat16& b1,
                                       __nv_bfloat16& b2, __nv_bfloat16& b3) {
    b1 = __float2bfloat16_rn(x);
    float r = x - __bfloat162float(b1);
    b2 = __float2bfloat16_rn(r);
    r -= __bfloat162float(b2);
    b3 = __float2bfloat16_rn(r);
}

// ---------------------------------------------------------------------------
// K1: gather embeddings
// ---------------------------------------------------------------------------
__global__ void gather_kernel(const int* __restrict__ tokens,
                              const int* __restrict__ ner,
                              const int* __restrict__ pos,
                              const float* __restrict__ encW,
                              const float* __restrict__ nerW,
                              const float* __restrict__ posW) {
    int r = blockIdx.x;
    int b = r & (BB - 1);
    int t = r >> 6;
    int tok = tokens[b * TT + t];
    int nid = ner[b * TT + t];
    int pid = pos[b * TT + t];
    float* dst = g_combined + (size_t)r * CIN;
    for (int c = threadIdx.x; c < CIN; c += blockDim.x) {
        float v;
        if (c < DD)             v = encW[(size_t)tok * DD + c];
        else if (c < DD + NNER) v = nerW[nid * NNER + (c - DD)];
        else                    v = posW[pid * NPOS + (c - DD - NNER)];
        dst[c] = v;
    }
}

// ---------------------------------------------------------------------------
// K2: generic tiled fp32 GEMM (pre-GEMMs)
// ---------------------------------------------------------------------------
template <bool TRANSB, bool ADDBIAS>
__global__ void gemm_tile(const float* __restrict__ A, const float* __restrict__ Bm,
                          const float* __restrict__ bias, float* __restrict__ C,
                          int M, int N, int K, int lda, int ldb, int ldc) {
    __shared__ __align__(16) float As[16 * 64];
    __shared__ __align__(16) float Bs[16 * 64];
    int tid = threadIdx.x;
    int m0 = blockIdx.y * 64;
    int n0 = blockIdx.x * 64;
    int mi = tid & 15;
    int ni = tid >> 4;
    float acc[4][4] = {};

    for (int k0 = 0; k0 < K; k0 += 16) {
        __syncthreads();
        #pragma unroll
        for (int i = 0; i < 4; i++) {
            int e = tid + 256 * i;
            int m = e >> 4, k = e & 15;
            int kk = k0 + k;
            float v = 0.f;
            if (kk < K) v = A[(size_t)(m0 + m) * lda + kk];
            As[k * 64 + m] = v;
        }
        #pragma unroll
        for (int i = 0; i < 4; i++) {
            int e = tid + 256 * i;
            float v = 0.f;
            if (TRANSB) {
                int n = e >> 4, k = e & 15;
                int kk = k0 + k, nn = n0 + n;
                if (kk < K && nn < N) v = Bm[(size_t)nn * ldb + kk];
                Bs[k * 64 + n] = v;
            } else {
                int k = e >> 6, n = e & 63;
                int kk = k0 + k, nn = n0 + n;
                if (kk < K && nn < N) v = Bm[(size_t)kk * ldb + nn];
                Bs[k * 64 + n] = v;
            }
        }
        __syncthreads();
        #pragma unroll
        for (int k = 0; k < 16; k++) {
            float4 a4 = *(const float4*)(As + k * 64 + mi * 4);
            float4 b4 = *(const float4*)(Bs + k * 64 + ni * 4);
            acc[0][0] = fmaf(a4.x, b4.x, acc[0][0]);
            acc[0][1] = fmaf(a4.x, b4.y, acc[0][1]);
            acc[0][2] = fmaf(a4.x, b4.z, acc[0][2]);
            acc[0][3] = fmaf(a4.x, b4.w, acc[0][3]);
            acc[1][0] = fmaf(a4.y, b4.x, acc[1][0]);
            acc[1][1] = fmaf(a4.y, b4.y, acc[1][1]);
            acc[1][2] = fmaf(a4.y, b4.z, acc[1][2]);
            acc[1][3] = fmaf(a4.y, b4.w, acc[1][3]);
            acc[2][0] = fmaf(a4.z, b4.x, acc[2][0]);
            acc[2][1] = fmaf(a4.z, b4.y, acc[2][1]);
            acc[2][2] = fmaf(a4.z, b4.z, acc[2][2]);
            acc[2][3] = fmaf(a4.z, b4.w, acc[2][3]);
            acc[3][0] = fmaf(a4.w, b4.x, acc[3][0]);
            acc[3][1] = fmaf(a4.w, b4.y, acc[3][1]);
            acc[3][2] = fmaf(a4.w, b4.z, acc[3][2]);
            acc[3][3] = fmaf(a4.w, b4.w, acc[3][3]);
        }
    }
    #pragma unroll
    for (int r = 0; r < 4; r++) {
        int mm = m0 + mi * 4 + r;
        #pragma unroll
        for (int c = 0; c < 4; c++) {
            int nn = n0 + ni * 4 + c;
            if (nn < N) {
                float v = acc[r][c];
                if (ADDBIAS) v += bias[nn];
                C[(size_t)mm * ldc + nn] = v;
            }
        }
    }
}

// ---------------------------------------------------------------------------
// K3: pack recurrent weights transposed + 3-way split.
// block = mat*D2 + col ; threads stride over k.
// ---------------------------------------------------------------------------
__global__ void pack_wt(const float* __restrict__ W0, const float* __restrict__ Ws) {
    int col = blockIdx.x % D2;
    int mat = blockIdx.x / D2;
    const float* W = (mat == 0) ? (W0 + (size_t)DD * D2)
                                : (Ws + (size_t)(mat - 1) * DD * D2);
    int half = (col >= DD) ? 1 : 0;
    int np = col - half * DD;
    size_t base = ((size_t)(mat * 2 + half) * 864 + np) * SD;
    for (int k = threadIdx.x; k < DD; k += blockDim.x) {
        float w = W[(size_t)k * D2 + col];
        __nv_bfloat16 b1, b2, b3;
        split3(w, b1, b2, b3);
        g_wt[0][base + k] = b1;
        g_wt[1][base + k] = b2;
        g_wt[2][base + k] = b3;
    }
}

// ---------------------------------------------------------------------------
// One tile-job via wmma. warp w: rows rs*16..+15 (rs = w&3), half ng = w>>2.
// W indexed by si.wmat (BUGFIX: was level-local `mat` in R5/R6/R7).
// ---------------------------------------------------------------------------
__device__ __forceinline__ void do_tile(
    int t, int sid, int mat, int tile, int kh, int sk)
{
    const StepInfo si = c_steps[sid];
    const int asrc = (si.pred < 0) ? 9 : si.pred;
    const float* __restrict__ Afp = (si.pred < 0) ? g_hprev : g_state[si.pred];
    const __nv_bfloat16* __restrict__ A1 = g_as[asrc][0];
    const __nv_bfloat16* __restrict__ A2 = g_as[asrc][1];
    const __nv_bfloat16* __restrict__ A3 = g_as[asrc][2];

    const int tid = threadIdx.x;
    const int w = tid >> 5;
    const int rs = w & 3;
    const int ng = w >> 2;
    const int m0 = rs * 16;
    const int ktb = (NKT * kh) / sk;
    const int kte = (NKT * (kh + 1)) / sk;
    // *** THE FIX: weight base uses si.wmat, not the level-local mat slot ***
    const size_t wbase = ((size_t)(si.wmat * 2 + ng) * 864 + tile * 16) * SD;

    wmma::fragment<wmma::accumulator, 16, 16, 16, float> fc;
    wmma::fill_fragment(fc, 0.0f);

    for (int kt = ktb; kt < kte; ++kt) {
        const int k0 = kt * 16;
        wmma::fragment<wmma::matrix_a, 16, 16, 16, __nv_bfloat16, wmma::row_major> fa1, fa2, fa3;
        wmma::fragment<wmma::matrix_b, 16, 16, 16, __nv_bfloat16, wmma::col_major> fb1, fb2, fb3;
        wmma::load_matrix_sync(fa1, A1 + (size_t)m0 * SD + k0, SD);
        wmma::load_matrix_sync(fa2, A2 + (size_t)m0 * SD + k0, SD);
        wmma::load_matrix_sync(fa3, A3 + (size_t)m0 * SD + k0, SD);
        wmma::load_matrix_sync(fb1, g_wt[0] + wbase + k0, SD);
        wmma::load_matrix_sync(fb2, g_wt[1] + wbase + k0, SD);
        wmma::load_matrix_sync(fb3, g_wt[2] + wbase + k0, SD);
        wmma::mma_sync(fc, fa1, fb1, fc);   // x1*w1
        wmma::mma_sync(fc, fa1, fb2, fc);   // x1*w2
        wmma::mma_sync(fc, fa2, fb1, fc);   // x2*w1
        wmma::mma_sync(fc, fa1, fb3, fc);   // x1*w3
        wmma::mma_sync(fc, fa2, fb2, fc);   // x2*w2
        wmma::mma_sync(fc, fa3, fb1, fc);   // x3*w1
    }

    float* pt = g_part[mat][kh];
    wmma::store_matrix_sync(pt + (size_t)m0 * PD2 + (ng ? 864 : 0) + tile * 16,
                            fc, PD2, wmma::mem_row_major);

    __shared__ int s_old;
    __threadfence();
    __syncthreads();
    if (tid == 0) s_old = atomicAdd(&g_cnt[mat][tile], 1);
    __syncthreads();
    if (s_old == sk - 1) {
        __threadfence();
        const int q = tid & 7;
        const int mq = tid >> 3;
        const int p0 = tile * 16 + 2 * q;
        if (p0 < DD) {
            #pragma unroll
            for (int h2 = 0; h2 < 2; ++h2) {
                int m = mq + h2 * 32;
                float vv[2];
                #pragma unroll
                for (int e = 0; e < 2; ++e) {
                    int p = p0 + e;
                    float cc = 0.f, hh = 0.f;
                    for (int q2 = 0; q2 < sk; ++q2) {
                        cc += g_part[mat][q2][(size_t)m * PD2 + p];
                        hh += g_part[mat][q2][(size_t)m * PD2 + 864 + p];
                    }
                    if (si.pred < 0) {
                        const float* xw = g_xw0 + ((size_t)t * BB + m) * D2;
                        cc += __ldcs(xw + p);
                        hh += __ldcs(xw + DD + p);
                    }
                    float sp = Afp[(size_t)m * SD + p];
                    float g = 1.f / (1.f + expf(-cc));
                    float av = (si.act == 0) ? tanhf(hh)
                             : (si.act == 1) ? fmaxf(hh, 0.f)
                             : (si.act == 2) ? 1.f / (1.f + expf(-hh)) : hh;
                    vv[e] = sp + g * (av - sp);
                }
                *(float2*)&g_state[sid][(size_t)m * SD + p0] = make_float2(vv[0], vv[1]);
                __nv_bfloat16 a1, a2, a3, b1, b2, b3;
                split3(vv[0], a1, a2, a3);
                split3(vv[1], b1, b2, b3);
                __nv_bfloat162 t1, t2, t3;
                t1.x = a1; t1.y = b1;
                t2.x = a2; t2.y = b2;
                t3.x = a3; t3.y = b3;
                *(__nv_bfloat162*)&g_as[sid][0][(size_t)m * SD + p0] = t1;
                *(__nv_bfloat162*)&g_as[sid][1][(size_t)m * SD + p0] = t2;
                *(__nv_bfloat162*)&g_as[sid][2][(size_t)m * SD + p0] = t3;
            }
        }
        __syncthreads();
        if (tid == 0) g_cnt[mat][tile] = 0;
    }
    __syncthreads();
}

__global__ __launch_bounds__(256, 2)
void recur_persist(const float* __restrict__ hidden) {
    const int bid = blockIdx.x;
    const int G = gridDim.x;
    const int tid = threadIdx.x;

    for (int t = 0; t < TT; ++t) {
        // prep: hprev = (t==0) ? hidden : mean(s1..s8); emit hiddens[t-1]; splits
        for (int i = bid * 256 + tid; i < BB * 425; i += G * 256) {
            int m = i / 425;
            int qd = i - m * 425;
            int d0 = 2 * qd;
            float v0, v1;
            if (t == 0) {
                v0 = hidden[m * DD + d0];
                v1 = hidden[m * DD + d0 + 1];
            } else {
                float s0 = 0.f, s1 = 0.f;
                #pragma unroll
                for (int j = 1; j <= 8; j++) {
                    s0 += g_state[j][m * SD + d0];
                    s1 += g_state[j][m * SD + d0 + 1];
                }
                v0 = s0 * 0.125f;
                v1 = s1 * 0.125f;
                __stcs(&g_hiddens[(size_t)(t - 1) * BB * DD + m * DD + d0], v0);
                __stcs(&g_hiddens[(size_t)(t - 1) * BB * DD + m * DD + d0 + 1], v1);
            }
            *(float2*)&g_hprev[m * SD + d0] = make_float2(v0, v1);
            __nv_bfloat16 a1, a2, a3, b1, b2, b3;
            split3(v0, a1, a2, a3);
            split3(v1, b1, b2, b3);
            __nv_bfloat162 t1, t2, t3;
            t1.x = a1; t1.y = b1;
            t2.x = a2; t2.y = b2;
            t3.x = a3; t3.y = b3;
            *(__nv_bfloat162*)&g_as[9][0][(size_t)m * SD + d0] = t1;
            *(__nv_bfloat162*)&g_as[9][1][(size_t)m * SD + d0] = t2;
            *(__nv_bfloat162*)&g_as[9][2][(size_t)m * SD + d0] = t3;
        }
        grid_sync();

        #pragma unroll
        for (int lvl = 0; lvl < 5; ++lvl) {
            const int nm = c_nm[lvl];
            const int sk = c_sk[lvl];
            const int jobs = nm * sk * NTILE;
            for (int j = bid; j < jobs; j += G) {
                int tile = j % NTILE;
                int r = j / NTILE;
                int kh = r % sk;
                int mat = r / sk;
                do_tile(t, c_sid[lvl][mat], mat, tile, kh, sk);
            }
            grid_sync();
        }
    }
}

// ---------------------------------------------------------------------------
// K5: mean over T, decoder, log_softmax, new_hidden.
// ---------------------------------------------------------------------------
__global__ void final_kernel(const float* __restrict__ masks,
                             const float* __restrict__ decW,
                             const float* __restrict__ decb,
                             float* __restrict__ out) {
    int b = blockIdx.x;
    int tid = threadIdx.x;
    __shared__ float sout[DD];
    __shared__ float lg[NCC];
    __shared__ float lse;

    float mask_last = masks[b * TT + TT - 1];
    for (int d = tid; d < DD; d += blockDim.x) {
        float ms = 0.f;
        #pragma unroll
        for (int j = 1; j <= 8; j++) ms += g_state[j][b * SD + d];
        ms *= 0.125f;
        float last_raw = ms * mask_last;
        float acc = last_raw;
        for (int t = 0; t < TT - 1; t++)
            acc += g_hiddens[(size_t)t * BB * DD + b * DD + d] * masks[b * TT + t];
        sout[d] = acc * (1.f / TT);
        out[NCC * BB + b * DD + d] = last_raw;
    }
    __syncthreads();

    for (int c = tid; c < NCC; c += blockDim.x) {
        float acc = decb[c];
        const float* w = decW + (size_t)c * DD;
        for (int d = 0; d < DD; d++) acc = fmaf(sout[d], w[d], acc);
        lg[c] = acc;
    }
    __syncthreads();

    if (tid == 0) {
        float mx = lg[0];
        for (int c = 1; c < NCC; c++) mx = fmaxf(mx, lg[c]);
        float s = 0.f;
        for (int c = 0; c < NCC; c++) s += expf(lg[c] - mx);
        lse = mx + logf(s);
    }
    __syncthreads();

    for (int c = tid; c < NCC; c += blockDim.x)
        out[b * NCC + c] = lg[c] - lse;
}

// ---------------------------------------------------------------------------
// Host launcher
// ---------------------------------------------------------------------------
extern "C" void kernel_launch(void* const* d_in, const int* in_sizes, int n_in,
                              void* d_out, int out_size) {
    const int*   tokens = (const int*)  d_in[0];
    const float* masks  = (const float*)d_in[1];
    const int*   pos    = (const int*)  d_in[2];
    const int*   ner    = (const int*)  d_in[3];
    const float* hidden = (const float*)d_in[4];
    const float* encW   = (const float*)d_in[5];
    const float* nerW   = (const float*)d_in[6];
    const float* posW   = (const float*)d_in[7];
    const float* aggW   = (const float*)d_in[8];
    const float* aggb   = (const float*)d_in[9];
    const float* W0     = (const float*)d_in[10];
    const float* Ws     = (const float*)d_in[11];
    const float* decW   = (const float*)d_in[12];
    const float* decb   = (const float*)d_in[13];
    float* out = (float*)d_out;

    static int s_grid = 0;
    if (s_grid == 0) {
        int dev = 0;
        cudaGetDevice(&dev);
        cudaDeviceProp prop;
        cudaGetDeviceProperties(&prop, dev);
        s_grid = 2 * prop.multiProcessorCount;   // co-resident via launch_bounds(256,2)
    }

    float *p_combined, *p_x, *p_xw0;
    cudaGetSymbolAddress((void**)&p_combined, g_combined);
    cudaGetSymbolAddress((void**)&p_x,        g_x);
    cudaGetSymbolAddress((void**)&p_xw0,      g_xw0);

    // 1) gather embeddings + pack weights (independent)
    gather_kernel<<<TT * BB, 128>>>(tokens, ner, pos, encW, nerW, posW);
    pack_wt<<<9 * D2, 128>>>(W0, Ws);

    // 2) agg linear: x = combined @ aggW^T + aggb   [8192, 850]
    {
        dim3 g((DD + 63) / 64, (TT * BB) / 64);
        gemm_tile<true, true><<<g, 256>>>(p_combined, aggW, aggb, p_x,
                                          TT * BB, DD, CIN, CIN, CIN, DD);
    }
    // 3) xw0 = x @ W0[0:DD, :]   [8192, 1700]
    {
        dim3 g((D2 + 63) / 64, (TT * BB) / 64);
        gemm_tile<false, false><<<g, 256>>>(p_x, W0, nullptr, p_xw0,
                                            TT * BB, D2, DD, DD, D2, D2);
    }

    // 4) whole recurrence in ONE persistent kernel
    recur_persist<<<s_grid, 256>>>(hidden);

    // 5) mean over T, decoder, log_softmax, new_hidden
    final_kernel<<<BB, 256>>>(masks, decW, decb, out);
}

// round 11
// speedup vs baseline: 1.2593x; 1.2593x over previous
#include <cuda_runtime.h>
#include <cuda_bf16.h>
#include <math.h>
#include <stdint.h>

#define BB   64
#define TT   128
#define DD   850
#define D2   1700
#define CIN  910
#define NCC  42
#define NNER 30
#define NPOS 30
#define SD   864          // padded state stride; cols >= 850 stay zero
#define NTILE 54          // 16-col pair tiles (54*16 = 864)
#define NKT  54           // k16 tiles
#define PD2  1728         // padded partial width (c at 0, h at 864)
#define KQ   432          // k-pairs per row (SD/2)

// Scratch (device globals zero-initialized; pad regions never written)
__device__ float g_combined[TT * BB * CIN];
__device__ float g_x[TT * BB * DD];
__device__ float g_xw0[TT * BB * D2];
__device__ float g_hiddens[TT * BB * DD];
__device__ float g_state[9][BB * SD];
__device__ float g_hprev[BB * SD];
__device__ __align__(256) float g_part[3][5][BB * PD2];
__device__ int   g_cnt[3][NTILE];
__device__ unsigned g_bar_cnt;
__device__ unsigned g_bar_gen;
// W fragments: idx = ((wmat*NKT+kt)*NTILE+tile)*4 + ns, per lane.
// g_Wf4 = {b0_t1, b1_t1, b0_t2, b1_t2}; g_Wf2 = {b0_t3, b1_t3}
__device__ __align__(256) uint4 g_Wf4[9 * NKT * NTILE * 4 * 32];
__device__ __align__(256) uint2 g_Wf2[9 * NKT * NTILE * 4 * 32];
// Pre-split A (states 0..8, hprev=9): 3 bf16 terms, packed pairs over k.
__device__ __align__(256) uint32_t g_abf[10][3][BB * KQ];

struct StepInfo { int wmat; int pred; int act; };
// act: 0 tanh, 1 relu, 2 sigmoid, 3 identity
__constant__ StepInfo c_steps[9] = {
    {0, -1, 0}, {1, 0, 2}, {2, 1, 1}, {3, 1, 1}, {4, 1, 3},
    {5, 2, 0}, {6, 5, 2}, {7, 3, 0}, {8, 5, 1},
};
// Levels: {s0},{s1},{s2,s3,s4},{s5},{s6,s7,s8}
__constant__ int c_nm[5]     = {1, 1, 3, 1, 3};
__constant__ int c_sk[5]     = {5, 5, 3, 5, 3};
__constant__ int c_sid[5][3] = {{0,0,0},{1,1,1},{2,3,4},{5,5,5},{6,7,8}};

// Sense-reversing grid barrier (all CTAs co-resident).
__device__ __forceinline__ void grid_sync() {
    __syncthreads();
    if (threadIdx.x == 0) {
        __threadfence();
        volatile unsigned* vg = &g_bar_gen;
        unsigned gen = *vg;
        if (atomicAdd(&g_bar_cnt, 1u) == gridDim.x - 1) {
            g_bar_cnt = 0;
            __threadfence();
            atomicExch(&g_bar_gen, gen + 1u);
        } else {
            while (*vg == gen) { __nanosleep(64); }
        }
        __threadfence();
    }
    __syncthreads();
}

// 3-way bf16 split of a value pair -> 3 packed bf16x2 words (x low, y high).
__device__ __forceinline__ void split3_pair(float x, float y,
        uint32_t& u1, uint32_t& u2, uint32_t& u3) {
    __nv_bfloat162 b1 = __floats2bfloat162_rn(x, y);
    float rx = x - __bfloat162float(__low2bfloat16(b1));
    float ry = y - __bfloat162float(__high2bfloat16(b1));
    __nv_bfloat162 b2 = __floats2bfloat162_rn(rx, ry);
    float rx2 = rx - __bfloat162float(__low2bfloat16(b2));
    float ry2 = ry - __bfloat162float(__high2bfloat16(b2));
    __nv_bfloat162 b3 = __floats2bfloat162_rn(rx2, ry2);
    u1 = *(uint32_t*)&b1; u2 = *(uint32_t*)&b2; u3 = *(uint32_t*)&b3;
}

__device__ __forceinline__ void mma_bf16(float* c, const uint32_t* a,
                                         uint32_t b0, uint32_t b1) {
    asm volatile(
        "mma.sync.aligned.m16n8k16.row.col.f32.bf16.bf16.f32 "
        "{%0,%1,%2,%3}, {%4,%5,%6,%7}, {%8,%9}, {%0,%1,%2,%3};"
        : "+f"(c[0]), "+f"(c[1]), "+f"(c[2]), "+f"(c[3])
        : "r"(a[0]), "r"(a[1]), "r"(a[2]), "r"(a[3]), "r"(b0), "r"(b1));
}

// ---------------------------------------------------------------------------
// K1: gather embeddings
// ---------------------------------------------------------------------------
__global__ void gather_kernel(const int* __restrict__ tokens,
                              const int* __restrict__ ner,
                              const int* __restrict__ pos,
                              const float* __restrict__ encW,
                              const float* __restrict__ nerW,
                              const float* __restrict__ posW) {
    int r = blockIdx.x;
    int b = r & (BB - 1);
    int t = r >> 6;
    int tok = tokens[b * TT + t];
    int nid = ner[b * TT + t];
    int pid = pos[b * TT + t];
    float* dst = g_combined + (size_t)r * CIN;
    for (int c = threadIdx.x; c < CIN; c += blockDim.x) {
        float v;
        if (c < DD)             v = encW[(size_t)tok * DD + c];
        else if (c < DD + NNER) v = nerW[nid * NNER + (c - DD)];
        else                    v = posW[pid * NPOS + (c - DD - NNER)];
        dst[c] = v;
    }
}

// ---------------------------------------------------------------------------
// K2: generic tiled fp32 GEMM (pre-GEMMs)
// ---------------------------------------------------------------------------
template <bool TRANSB, bool ADDBIAS>
__global__ void gemm_tile(const float* __restrict__ A, const float* __restrict__ Bm,
                          const float* __restrict__ bias, float* __restrict__ C,
                          int M, int N, int K, int lda, int ldb, int ldc) {
    __shared__ __align__(16) float As[16 * 64];
    __shared__ __align__(16) float Bs[16 * 64];
    int tid = threadIdx.x;
    int m0 = blockIdx.y * 64;
    int n0 = blockIdx.x * 64;
    int mi = tid & 15;
    int ni = tid >> 4;
    float acc[4][4] = {};

    for (int k0 = 0; k0 < K; k0 += 16) {
        __syncthreads();
        #pragma unroll
        for (int i = 0; i < 4; i++) {
            int e = tid + 256 * i;
            int m = e >> 4, k = e & 15;
            int kk = k0 + k;
            float v = 0.f;
            if (kk < K) v = A[(size_t)(m0 + m) * lda + kk];
            As[k * 64 + m] = v;
        }
        #pragma unroll
        for (int i = 0; i < 4; i++) {
            int e = tid + 256 * i;
            float v = 0.f;
            if (TRANSB) {
                int n = e >> 4, k = e & 15;
                int kk = k0 + k, nn = n0 + n;
                if (kk < K && nn < N) v = Bm[(size_t)nn * ldb + kk];
                Bs[k * 64 + n] = v;
            } else {
                int k = e >> 6, n = e & 63;
                int kk = k0 + k, nn = n0 + n;
                if (kk < K && nn < N) v = Bm[(size_t)kk * ldb + nn];
                Bs[k * 64 + n] = v;
            }
        }
        __syncthreads();
        #pragma unroll
        for (int k = 0; k < 16; k++) {
            float4 a4 = *(const float4*)(As + k * 64 + mi * 4);
            float4 b4 = *(const float4*)(Bs + k * 64 + ni * 4);
            acc[0][0] = fmaf(a4.x, b4.x, acc[0][0]);
            acc[0][1] = fmaf(a4.x, b4.y, acc[0][1]);
            acc[0][2] = fmaf(a4.x, b4.z, acc[0][2]);
            acc[0][3] = fmaf(a4.x, b4.w, acc[0][3]);
            acc[1][0] = fmaf(a4.y, b4.x, acc[1][0]);
            acc[1][1] = fmaf(a4.y, b4.y, acc[1][1]);
            acc[1][2] = fmaf(a4.y, b4.z, acc[1][2]);
            acc[1][3] = fmaf(a4.y, b4.w, acc[1][3]);
            acc[2][0] = fmaf(a4.z, b4.x, acc[2][0]);
            acc[2][1] = fmaf(a4.z, b4.y, acc[2][1]);
            acc[2][2] = fmaf(a4.z, b4.z, acc[2][2]);
            acc[2][3] = fmaf(a4.z, b4.w, acc[2][3]);
            acc[3][0] = fmaf(a4.w, b4.x, acc[3][0]);
            acc[3][1] = fmaf(a4.w, b4.y, acc[3][1]);
            acc[3][2] = fmaf(a4.w, b4.z, acc[3][2]);
            acc[3][3] = fmaf(a4.w, b4.w, acc[3][3]);
        }
    }
    #pragma unroll
    for (int r = 0; r < 4; r++) {
        int mm = m0 + mi * 4 + r;
        #pragma unroll
        for (int c = 0; c < 4; c++) {
            int nn = n0 + ni * 4 + c;
            if (nn < N) {
                float v = acc[r][c];
                if (ADDBIAS) v += bias[nn];
                C[(size_t)mm * ldc + nn] = v;
            }
        }
    }
}

// ---------------------------------------------------------------------------
// K3: pack recurrent weights into 3-term bf16 mma-fragment layout.
// block = (wmat*NKT + kt)*NTILE + pt ; 128 threads = 4 nsubs x 32 lanes.
// ---------------------------------------------------------------------------
__global__ void pack_w(const float* __restrict__ W0, const float* __restrict__ Ws) {
    int id = blockIdx.x;
    int pt = id % NTILE;
    int kt = (id / NTILE) % NKT;
    int mat = id / (NTILE * NKT);
    int ns = threadIdx.x >> 5;
    int lane = threadIdx.x & 31;
    const float* W = (mat == 0) ? (W0 + (size_t)DD * D2)
                                : (Ws + (size_t)(mat - 1) * DD * D2);
    int half = ns >> 1;
    int col = pt * 16 + (ns & 1) * 8 + (lane >> 2);
    int gcol = (col < DD) ? (half ? DD + col : col) : -1;
    int k0 = kt * 16 + (lane & 3) * 2;
    float v[4];
    #pragma unroll
    for (int j = 0; j < 4; ++j) {
        int k = k0 + (j & 1) + (j >> 1) * 8;   // k0, k0+1, k0+8, k0+9
        v[j] = (gcol >= 0 && k < DD) ? W[(size_t)k * D2 + gcol] : 0.f;
    }
    uint32_t a1, a2, a3, b1, b2, b3;
    split3_pair(v[0], v[1], a1, a2, a3);
    split3_pair(v[2], v[3], b1, b2, b3);
    size_t idx = ((size_t)id * 4 + ns) * 32 + lane;
    g_Wf4[idx] = make_uint4(a1, b1, a2, b2);
    g_Wf2[idx] = make_uint2(a3, b3);
}

// ---------------------------------------------------------------------------
// One tile-job: C[64 x (16c+16h)] over k-range via 6-pass triple-split mma.
// warp w: rows rs = w&3 (16 rows), ng = w>>2 (0 = c half, 1 = h half).
// W base indexed by si.wmat (BUGFIX vs R6: was level-local `mat`).
// ---------------------------------------------------------------------------
__device__ __forceinline__ void do_tile(
    int t, int sid, int mat, int tile, int kh, int sk)
{
    const StepInfo si = c_steps[sid];
    const int asrc = (si.pred < 0) ? 9 : si.pred;
    const float* __restrict__ Afp = (si.pred < 0) ? g_hprev : g_state[si.pred];

    const int tid = threadIdx.x;
    const int lane = tid & 31;
    const int w = tid >> 5;
    const int rs = w & 3;
    const int ng = w >> 2;

    const int ktb = (NKT * kh) / sk;
    const int kte = (NKT * (kh + 1)) / sk;

    const int r0 = rs * 16 + (lane >> 2);
    const int ro = r0 * KQ;
    const int r8 = ro + 8 * KQ;
    const int qk = lane & 3;

    const uint32_t* __restrict__ A1 = g_abf[asrc][0];
    const uint32_t* __restrict__ A2 = g_abf[asrc][1];
    const uint32_t* __restrict__ A3 = g_abf[asrc][2];

    float c0[4] = {0.f, 0.f, 0.f, 0.f};
    float c1[4] = {0.f, 0.f, 0.f, 0.f};

    for (int kt = ktb; kt < kte; ++kt) {
        const int kq = kt * 8 + qk;
        uint32_t a1[4] = {A1[ro + kq], A1[r8 + kq], A1[ro + kq + 4], A1[r8 + kq + 4]};
        uint32_t a2[4] = {A2[ro + kq], A2[r8 + kq], A2[ro + kq + 4], A2[r8 + kq + 4]};
        uint32_t a3[4] = {A3[ro + kq], A3[r8 + kq], A3[ro + kq + 4], A3[r8 + kq + 4]};

        // *** FIX: fragment base uses si.wmat (weight id), not partial slot ***
        size_t wb = ((size_t)((si.wmat * NKT + kt) * NTILE + tile) * 4 + ng * 2) * 32 + lane;
        uint4 w40 = g_Wf4[wb];
        uint4 w41 = g_Wf4[wb + 32];
        uint2 w20 = g_Wf2[wb];
        uint2 w21 = g_Wf2[wb + 32];

        mma_bf16(c0, a1, w40.x, w40.y);   // x1*w1
        mma_bf16(c0, a1, w40.z, w40.w);   // x1*w2
        mma_bf16(c0, a2, w40.x, w40.y);   // x2*w1
        mma_bf16(c0, a1, w20.x, w20.y);   // x1*w3
        mma_bf16(c0, a2, w40.z, w40.w);   // x2*w2
        mma_bf16(c0, a3, w40.x, w40.y);   // x3*w1

        mma_bf16(c1, a1, w41.x, w41.y);
        mma_bf16(c1, a1, w41.z, w41.w);
        mma_bf16(c1, a2, w41.x, w41.y);
        mma_bf16(c1, a1, w21.x, w21.y);
        mma_bf16(c1, a2, w41.z, w41.w);
        mma_bf16(c1, a3, w41.x, w41.y);
    }

    // write partials (fragment layout -> padded [64][1728] buffer)
    {
        float* pt = g_part[mat][kh];
        int row = rs * 16 + (lane >> 2);
        int colb = (ng ? 864 : 0) + tile * 16;
        int col0 = colb + (lane & 3) * 2;
        int col1 = colb + 8 + (lane & 3) * 2;
        *(float2*)&pt[(size_t)row * PD2 + col0]       = make_float2(c0[0], c0[1]);
        *(float2*)&pt[(size_t)(row + 8) * PD2 + col0] = make_float2(c0[2], c0[3]);
        *(float2*)&pt[(size_t)row * PD2 + col1]       = make_float2(c1[0], c1[1]);
        *(float2*)&pt[(size_t)(row + 8) * PD2 + col1] = make_float2(c1[2], c1[3]);
    }

    __shared__ int s_old;
    __threadfence();
    __syncthreads();
    if (tid == 0) s_old = atomicAdd(&g_cnt[mat][tile], 1);
    __syncthreads();
    if (s_old == sk - 1) {
        __threadfence();
        // epilogue: threads handle (2 rows) x (2 adjacent cols) = 4 elems
        const int q = tid & 7;
        const int mq = tid >> 3;
        const int p0 = tile * 16 + 2 * q;
        if (p0 < DD) {
            #pragma unroll
            for (int h2 = 0; h2 < 2; ++h2) {
                int m = mq + h2 * 32;
                float vv[2];
                #pragma unroll
                for (int e = 0; e < 2; ++e) {
                    int p = p0 + e;
                    float cc = 0.f, hh = 0.f;
                    for (int q2 = 0; q2 < sk; ++q2) {
                        cc += g_part[mat][q2][(size_t)m * PD2 + p];
                        hh += g_part[mat][q2][(size_t)m * PD2 + 864 + p];
                    }
                    if (si.pred < 0) {
                        const float* xw = g_xw0 + ((size_t)t * BB + m) * D2;
                        cc += __ldcs(xw + p);
                        hh += __ldcs(xw + DD + p);
                    }
                    float sp = Afp[(size_t)m * SD + p];
                    float g = 1.f / (1.f + expf(-cc));
                    float av = (si.act == 0) ? tanhf(hh)
                             : (si.act == 1) ? fmaxf(hh, 0.f)
                             : (si.act == 2) ? 1.f / (1.f + expf(-hh)) : hh;
                    vv[e] = sp + g * (av - sp);
                }
                *(float2*)&g_state[sid][(size_t)m * SD + p0] = make_float2(vv[0], vv[1]);
                uint32_t u1, u2, u3;
                split3_pair(vv[0], vv[1], u1, u2, u3);
                int qi = m * KQ + (p0 >> 1);
                g_abf[sid][0][qi] = u1;
                g_abf[sid][1][qi] = u2;
                g_abf[sid][2][qi] = u3;
            }
        }
        __syncthreads();
        if (tid == 0) g_cnt[mat][tile] = 0;
    }
    __syncthreads();
}

__global__ __launch_bounds__(256, 2)
void recur_persist(const float* __restrict__ hidden) {
    const int bid = blockIdx.x;
    const int G = gridDim.x;
    const int tid = threadIdx.x;

    for (int t = 0; t < TT; ++t) {
        // prep: hprev pairs; emit hiddens[t-1]; write hprev splits
        for (int i = bid * 256 + tid; i < BB * 425; i += G * 256) {
            int m = i / 425;
            int qd = i - m * 425;
            int d0 = 2 * qd;
            float v0, v1;
            if (t == 0) {
                v0 = hidden[m * DD + d0];
                v1 = hidden[m * DD + d0 + 1];
            } else {
                float s0 = 0.f, s1 = 0.f;
                #pragma unroll
                for (int j = 1; j <= 8; j++) {
                    s0 += g_state[j][m * SD + d0];
                    s1 += g_state[j][m * SD + d0 + 1];
                }
                v0 = s0 * 0.125f;
                v1 = s1 * 0.125f;
                __stcs(&g_hiddens[(size_t)(t - 1) * BB * DD + m * DD + d0], v0);
                __stcs(&g_hiddens[(size_t)(t - 1) * BB * DD + m * DD + d0 + 1], v1);
            }
            *(float2*)&g_hprev[m * SD + d0] = make_float2(v0, v1);
            uint32_t u1, u2, u3;
            split3_pair(v0, v1, u1, u2, u3);
            int qi = m * KQ + qd;
            g_abf[9][0][qi] = u1;
            g_abf[9][1][qi] = u2;
            g_abf[9][2][qi] = u3;
        }
        grid_sync();

        #pragma unroll
        for (int lvl = 0; lvl < 5; ++lvl) {
            const int nm = c_nm[lvl];
            const int sk = c_sk[lvl];
            const int jobs = nm * sk * NTILE;
            for (int j = bid; j < jobs; j += G) {
                int tile = j % NTILE;
                int r = j / NTILE;
                int kh = r % sk;
                int mat = r / sk;
                do_tile(t, c_sid[lvl][mat], mat, tile, kh, sk);
            }
            grid_sync();
        }
    }
}

// ---------------------------------------------------------------------------
// K5: mean over T, decoder, log_softmax, new_hidden.
// ---------------------------------------------------------------------------
__global__ void final_kernel(const float* __restrict__ masks,
                             const float* __restrict__ decW,
                             const float* __restrict__ decb,
                             float* __restrict__ out) {
    int b = blockIdx.x;
    int tid = threadIdx.x;
    __shared__ float sout[DD];
    __shared__ float lg[NCC];
    __shared__ float lse;

    float mask_last = masks[b * TT + TT - 1];
    for (int d = tid; d < DD; d += blockDim.x) {
        float ms = 0.f;
        #pragma unroll
        for (int j = 1; j <= 8; j++) ms += g_state[j][b * SD + d];
        ms *= 0.125f;
        float last_raw = ms * mask_last;
        float acc = last_raw;
        for (int t = 0; t < TT - 1; t++)
            acc += g_hiddens[(size_t)t * BB * DD + b * DD + d] * masks[b * TT + t];
        sout[d] = acc * (1.f / TT);
        out[NCC * BB + b * DD + d] = last_raw;
    }
    __syncthreads();

    for (int c = tid; c < NCC; c += blockDim.x) {
        float acc = decb[c];
        const float* w = decW + (size_t)c * DD;
        for (int d = 0; d < DD; d++) acc = fmaf(sout[d], w[d], acc);
        lg[c] = acc;
    }
    __syncthreads();

    if (tid == 0) {
        float mx = lg[0];
        for (int c = 1; c < NCC; c++) mx = fmaxf(mx, lg[c]);
        float s = 0.f;
        for (int c = 0; c < NCC; c++) s += expf(lg[c] - mx);
        lse = mx + logf(s);
    }
    __syncthreads();

    for (int c = tid; c < NCC; c += blockDim.x)
        out[b * NCC + c] = lg[c] - lse;
}

// ---------------------------------------------------------------------------
// Host launcher
// ---------------------------------------------------------------------------
extern "C" void kernel_launch(void* const* d_in, const int* in_sizes, int n_in,
                              void* d_out, int out_size) {
    const int*   tokens = (const int*)  d_in[0];
    const float* masks  = (const float*)d_in[1];
    const int*   pos    = (const int*)  d_in[2];
    const int*   ner    = (const int*)  d_in[3];
    const float* hidden = (const float*)d_in[4];
    const float* encW   = (const float*)d_in[5];
    const float* nerW   = (const float*)d_in[6];
    const float* posW   = (const float*)d_in[7];
    const float* aggW   = (const float*)d_in[8];
    const float* aggb   = (const float*)d_in[9];
    const float* W0     = (const float*)d_in[10];
    const float* Ws     = (const float*)d_in[11];
    const float* decW   = (const float*)d_in[12];
    const float* decb   = (const float*)d_in[13];
    float* out = (float*)d_out;

    static int s_grid = 0;
    if (s_grid == 0) {
        int dev = 0;
        cudaGetDevice(&dev);
        cudaDeviceProp prop;
        cudaGetDeviceProperties(&prop, dev);
        s_grid = 2 * prop.multiProcessorCount;   // co-resident via launch_bounds(256,2)
    }

    float *p_combined, *p_x, *p_xw0;
    cudaGetSymbolAddress((void**)&p_combined, g_combined);
    cudaGetSymbolAddress((void**)&p_x,        g_x);
    cudaGetSymbolAddress((void**)&p_xw0,      g_xw0);

    // 1) gather embeddings + pack weights (independent)
    gather_kernel<<<TT * BB, 128>>>(tokens, ner, pos, encW, nerW, posW);
    pack_w<<<9 * NKT * NTILE, 128>>>(W0, Ws);

    // 2) agg linear: x = combined @ aggW^T + aggb   [8192, 850]
    {
        dim3 g((DD + 63) / 64, (TT * BB) / 64);
        gemm_tile<true, true><<<g, 256>>>(p_combined, aggW, aggb, p_x,
                                          TT * BB, DD, CIN, CIN, CIN, DD);
    }
    // 3) xw0 = x @ W0[0:DD, :]   [8192, 1700]
    {
        dim3 g((D2 + 63) / 64, (TT * BB) / 64);
        gemm_tile<false, false><<<g, 256>>>(p_x, W0, nullptr, p_xw0,
                                            TT * BB, D2, DD, DD, D2, D2);
    }

    // 4) whole recurrence in ONE persistent kernel
    recur_persist<<<s_grid, 256>>>(hidden);

    // 5) mean over T, decoder, log_softmax, new_hidden
    final_kernel<<<BB, 256>>>(masks, decW, decb, out);
}

// round 12
// speedup vs baseline: 1.8275x; 1.4512x over previous
#include <cuda_runtime.h>
#include <cuda_bf16.h>
#include <math.h>
#include <stdint.h>

#define BB   64
#define TT   128
#define DD   850
#define D2   1700
#define CIN  910
#define NCC  42
#define NNER 30
#define NPOS 30
#define SD   864          // padded k stride; pads stay zero
#define NTILE 54          // 16-col pair tiles
#define NKT  54           // k16 tiles
#define KQ   432          // k-pairs per row (SD/2)

// Scratch (device globals zero-initialized; pad regions never written)
__device__ float g_combined[TT * BB * CIN];
__device__ float g_x[TT * BB * DD];
__device__ float g_xw0[TT * BB * D2];
__device__ float g_hiddens[TT * BB * DD];
__device__ float g_state[9][BB * SD];
__device__ float g_hprev[BB * SD];
__device__ int   g_tcnt[108];          // fold counters: mh*54 + tile
__device__ unsigned g_bar_cnt;
__device__ unsigned g_bar_gen;
// W fragments (2-way split): idx = ((wmat*NKT+kt)*NTILE+tile)*4 + ns, per lane.
// uint4 = {b0_t1, b1_t1, b0_t2, b1_t2}
__device__ __align__(256) uint4 g_Wf4[9 * NKT * NTILE * 4 * 32];
// Pre-split A (states 0..8, hprev=9): 2 bf16 terms, packed pairs over k.
__device__ __align__(256) uint32_t g_abf[10][2][BB * KQ];

struct StepInfo { int wmat; int pred; int act; };
// act: 0 tanh, 1 relu, 2 sigmoid, 3 identity
__constant__ StepInfo c_steps[9] = {
    {0, -1, 0}, {1, 0, 2}, {2, 1, 1}, {3, 1, 1}, {4, 1, 3},
    {5, 2, 0}, {6, 5, 2}, {7, 3, 0}, {8, 5, 1},
};
// Levels: {s0},{s1},{s2,s3,s4},{s5,s7},{s6,s8}
__constant__ int c_nm[5]     = {1, 1, 3, 2, 2};
__constant__ int c_sid[5][3] = {{0,0,0},{1,1,1},{2,3,4},{5,7,7},{6,8,8}};

// Sense-reversing grid barrier (1 CTA/SM => co-resident).
__device__ __forceinline__ void grid_sync() {
    __syncthreads();
    if (threadIdx.x == 0) {
        __threadfence();
        volatile unsigned* vg = &g_bar_gen;
        unsigned gen = *vg;
        if (atomicAdd(&g_bar_cnt, 1u) == gridDim.x - 1) {
            g_bar_cnt = 0;
            __threadfence();
            atomicExch(&g_bar_gen, gen + 1u);
        } else {
            while (*vg == gen) { __nanosleep(64); }
        }
        __threadfence();
    }
    __syncthreads();
}

// 2-way bf16 split of a value pair -> 2 packed bf16x2 words (x low, y high).
__device__ __forceinline__ void split2_pair(float x, float y,
        uint32_t& u1, uint32_t& u2) {
    __nv_bfloat162 b1 = __floats2bfloat162_rn(x, y);
    float rx = x - __bfloat162float(__low2bfloat16(b1));
    float ry = y - __bfloat162float(__high2bfloat16(b1));
    __nv_bfloat162 b2 = __floats2bfloat162_rn(rx, ry);
    u1 = *(uint32_t*)&b1; u2 = *(uint32_t*)&b2;
}

__device__ __forceinline__ void mma_bf16(float* c, const uint32_t* a,
                                         uint32_t b0, uint32_t b1) {
    asm volatile(
        "mma.sync.aligned.m16n8k16.row.col.f32.bf16.bf16.f32 "
        "{%0,%1,%2,%3}, {%4,%5,%6,%7}, {%8,%9}, {%0,%1,%2,%3};"
        : "+f"(c[0]), "+f"(c[1]), "+f"(c[2]), "+f"(c[3])
        : "r"(a[0]), "r"(a[1]), "r"(a[2]), "r"(a[3]), "r"(b0), "r"(b1));
}

// ---------------------------------------------------------------------------
// K1: gather embeddings
// ---------------------------------------------------------------------------
__global__ void gather_kernel(const int* __restrict__ tokens,
                              const int* __restrict__ ner,
                              const int* __restrict__ pos,
                              const float* __restrict__ encW,
                              const float* __restrict__ nerW,
                              const float* __restrict__ posW) {
    int r = blockIdx.x;
    int b = r & (BB - 1);
    int t = r >> 6;
    int tok = tokens[b * TT + t];
    int nid = ner[b * TT + t];
    int pid = pos[b * TT + t];
    float* dst = g_combined + (size_t)r * CIN;
    for (int c = threadIdx.x; c < CIN; c += blockDim.x) {
        float v;
        if (c < DD)             v = encW[(size_t)tok * DD + c];
        else if (c < DD + NNER) v = nerW[nid * NNER + (c - DD)];
        else                    v = posW[pid * NPOS + (c - DD - NNER)];
        dst[c] = v;
    }
}

// ---------------------------------------------------------------------------
// K2: generic tiled fp32 GEMM (pre-GEMMs)
// ---------------------------------------------------------------------------
template <bool TRANSB, bool ADDBIAS>
__global__ void gemm_tile(const float* __restrict__ A, const float* __restrict__ Bm,
                          const float* __restrict__ bias, float* __restrict__ C,
                          int M, int N, int K, int lda, int ldb, int ldc) {
    __shared__ __align__(16) float As[16 * 64];
    __shared__ __align__(16) float Bs[16 * 64];
    int tid = threadIdx.x;
    int m0 = blockIdx.y * 64;
    int n0 = blockIdx.x * 64;
    int mi = tid & 15;
    int ni = tid >> 4;
    float acc[4][4] = {};

    for (int k0 = 0; k0 < K; k0 += 16) {
        __syncthreads();
        #pragma unroll
        for (int i = 0; i < 4; i++) {
            int e = tid + 256 * i;
            int m = e >> 4, k = e & 15;
            int kk = k0 + k;
            float v = 0.f;
            if (kk < K) v = A[(size_t)(m0 + m) * lda + kk];
            As[k * 64 + m] = v;
        }
        #pragma unroll
        for (int i = 0; i < 4; i++) {
            int e = tid + 256 * i;
            float v = 0.f;
            if (TRANSB) {
                int n = e >> 4, k = e & 15;
                int kk = k0 + k, nn = n0 + n;
                if (kk < K && nn < N) v = Bm[(size_t)nn * ldb + kk];
                Bs[k * 64 + n] = v;
            } else {
                int k = e >> 6, n = e & 63;
                int kk = k0 + k, nn = n0 + n;
                if (kk < K && nn < N) v = Bm[(size_t)kk * ldb + nn];
                Bs[k * 64 + n] = v;
            }
        }
        __syncthreads();
        #pragma unroll
        for (int k = 0; k < 16; k++) {
            float4 a4 = *(const float4*)(As + k * 64 + mi * 4);
            float4 b4 = *(const float4*)(Bs + k * 64 + ni * 4);
            acc[0][0] = fmaf(a4.x, b4.x, acc[0][0]);
            acc[0][1] = fmaf(a4.x, b4.y, acc[0][1]);
            acc[0][2] = fmaf(a4.x, b4.z, acc[0][2]);
            acc[0][3] = fmaf(a4.x, b4.w, acc[0][3]);
            acc[1][0] = fmaf(a4.y, b4.x, acc[1][0]);
            acc[1][1] = fmaf(a4.y, b4.y, acc[1][1]);
            acc[1][2] = fmaf(a4.y, b4.z, acc[1][2]);
            acc[1][3] = fmaf(a4.y, b4.w, acc[1][3]);
            acc[2][0] = fmaf(a4.z, b4.x, acc[2][0]);
            acc[2][1] = fmaf(a4.z, b4.y, acc[2][1]);
            acc[2][2] = fmaf(a4.z, b4.z, acc[2][2]);
            acc[2][3] = fmaf(a4.z, b4.w, acc[2][3]);
            acc[3][0] = fmaf(a4.w, b4.x, acc[3][0]);
            acc[3][1] = fmaf(a4.w, b4.y, acc[3][1]);
            acc[3][2] = fmaf(a4.w, b4.z, acc[3][2]);
            acc[3][3] = fmaf(a4.w, b4.w, acc[3][3]);
        }
    }
    #pragma unroll
    for (int r = 0; r < 4; r++) {
        int mm = m0 + mi * 4 + r;
        #pragma unroll
        for (int c = 0; c < 4; c++) {
            int nn = n0 + ni * 4 + c;
            if (nn < N) {
                float v = acc[r][c];
                if (ADDBIAS) v += bias[nn];
                C[(size_t)mm * ldc + nn] = v;
            }
        }
    }
}

// ---------------------------------------------------------------------------
// K3: pack recurrent weights into 2-term bf16 mma-fragment layout.
// block = (wmat*NKT + kt)*NTILE + pt ; 128 threads = 4 nsubs x 32 lanes.
// ---------------------------------------------------------------------------
__global__ void pack_w(const float* __restrict__ W0, const float* __restrict__ Ws) {
    int id = blockIdx.x;
    int pt = id % NTILE;
    int kt = (id / NTILE) % NKT;
    int mat = id / (NTILE * NKT);
    int ns = threadIdx.x >> 5;
    int lane = threadIdx.x & 31;
    const float* W = (mat == 0) ? (W0 + (size_t)DD * D2)
                                : (Ws + (size_t)(mat - 1) * DD * D2);
    int half = ns >> 1;
    int col = pt * 16 + (ns & 1) * 8 + (lane >> 2);
    int gcol = (col < DD) ? (half ? DD + col : col) : -1;
    int k0 = kt * 16 + (lane & 3) * 2;
    float v[4];
    #pragma unroll
    for (int j = 0; j < 4; ++j) {
        int k = k0 + (j & 1) + (j >> 1) * 8;   // k0, k0+1, k0+8, k0+9
        v[j] = (gcol >= 0 && k < DD) ? W[(size_t)k * D2 + gcol] : 0.f;
    }
    uint32_t a1, a2, b1, b2;
    split2_pair(v[0], v[1], a1, a2);
    split2_pair(v[2], v[3], b1, b2);
    g_Wf4[((size_t)id * 4 + ns) * 32 + lane] = make_uint4(a1, b1, a2, b2);
}

// ---------------------------------------------------------------------------
// One job: C[32 rows x (16c+16h)] full-K, 3-pass 2-way-split mma.
// 8 warps = ng(2) x m16i(2) x khalf(2); khalf partials combined via smem.
// Level 4 jobs additionally fold next-step prep via per-(mh,tile) counter.
// ---------------------------------------------------------------------------
__device__ __forceinline__ void do_job(
    int t, int lvl, int j, float (*sm)[32][33], int* s_old)
{
    const int tile = j % NTILE;
    const int r = j / NTILE;
    const int mh = r & 1;
    const int mi = r >> 1;
    const int sid = c_sid[lvl][mi];
    const StepInfo si = c_steps[sid];
    const int asrc = (si.pred < 0) ? 9 : si.pred;
    const float* __restrict__ Afp = (si.pred < 0) ? g_hprev : g_state[si.pred];

    const int tid = threadIdx.x;
    const int lane = tid & 31;
    const int w = tid >> 5;
    const int ng = w & 1;
    const int m16i = (w >> 1) & 1;
    const int kh = w >> 2;

    const int r0g = mh * 32 + m16i * 16 + (lane >> 2);
    const int ro = r0g * KQ;
    const int r8 = ro + 8 * KQ;
    const int qk = lane & 3;

    const uint32_t* __restrict__ A1 = g_abf[asrc][0];
    const uint32_t* __restrict__ A2 = g_abf[asrc][1];

    float c0[4] = {0.f, 0.f, 0.f, 0.f};
    float c1[4] = {0.f, 0.f, 0.f, 0.f};

    const int ktb = kh * 27;
    #pragma unroll 3
    for (int kt = ktb; kt < ktb + 27; ++kt) {
        const int kq = kt * 8 + qk;
        uint32_t a1[4] = {A1[ro + kq], A1[r8 + kq], A1[ro + kq + 4], A1[r8 + kq + 4]};
        uint32_t a2[4] = {A2[ro + kq], A2[r8 + kq], A2[ro + kq + 4], A2[r8 + kq + 4]};
        size_t wb = ((size_t)((si.wmat * NKT + kt) * NTILE + tile) * 4 + ng * 2) * 32 + lane;
        uint4 w40 = g_Wf4[wb];
        uint4 w41 = g_Wf4[wb + 32];
        mma_bf16(c0, a1, w40.x, w40.y);   // x1*w1
        mma_bf16(c0, a1, w40.z, w40.w);   // x1*w2
        mma_bf16(c0, a2, w40.x, w40.y);   // x2*w1
        mma_bf16(c1, a1, w41.x, w41.y);
        mma_bf16(c1, a1, w41.z, w41.w);
        mma_bf16(c1, a2, w41.x, w41.y);
    }

    // store fragments to smem (khalf-partials)
    {
        const int rl = m16i * 16 + (lane >> 2);
        const int cb = ng * 16 + (lane & 3) * 2;
        sm[kh][rl][cb]         = c0[0];
        sm[kh][rl][cb + 1]     = c0[1];
        sm[kh][rl + 8][cb]     = c0[2];
        sm[kh][rl + 8][cb + 1] = c0[3];
        sm[kh][rl][cb + 8]         = c1[0];
        sm[kh][rl][cb + 9]         = c1[1];
        sm[kh][rl + 8][cb + 8]     = c1[2];
        sm[kh][rl + 8][cb + 9]     = c1[3];
    }
    __syncthreads();

    // epilogue: 256 threads = 32 rows x 8 col-pairs
    const int ml = tid >> 3;
    const int q = tid & 7;
    const int p0 = tile * 16 + 2 * q;
    const int m = mh * 32 + ml;
    if (p0 < DD) {
        float vv[2];
        #pragma unroll
        for (int e = 0; e < 2; ++e) {
            int cp = 2 * q + e;
            int p = p0 + e;
            float cc = sm[0][ml][cp] + sm[1][ml][cp];
            float hh = sm[0][ml][16 + cp] + sm[1][ml][16 + cp];
            if (si.pred < 0) {
                const float* xw = g_xw0 + ((size_t)t * BB + m) * D2;
                cc += __ldcs(xw + p);
                hh += __ldcs(xw + DD + p);
            }
            float sp = Afp[(size_t)m * SD + p];
            float g = 1.f / (1.f + expf(-cc));
            float av = (si.act == 0) ? tanhf(hh)
                     : (si.act == 1) ? fmaxf(hh, 0.f)
                     : (si.act == 2) ? 1.f / (1.f + expf(-hh)) : hh;
            vv[e] = sp + g * (av - sp);
        }
        *(float2*)&g_state[sid][(size_t)m * SD + p0] = make_float2(vv[0], vv[1]);
        uint32_t u1, u2;
        split2_pair(vv[0], vv[1], u1, u2);
        int qi = m * KQ + (p0 >> 1);
        g_abf[sid][0][qi] = u1;
        g_abf[sid][1][qi] = u2;
    }
    __syncthreads();   // smem reusable by next job

    // level-4 fold: when both mats (6,8) of this (mh,tile) block are done,
    // compute next-step hprev (+ hiddens[t]) for these rows/cols.
    if (lvl == 4) {
        __threadfence();
        __syncthreads();
        if (tid == 0) *s_old = atomicAdd(&g_tcnt[mh * 54 + tile], 1);
        __syncthreads();
        if (*s_old == 1) {
            __threadfence();
            if (p0 < DD) {
                float v0 = 0.f, v1 = 0.f;
                #pragma unroll
                for (int jj = 1; jj <= 8; ++jj) {
                    v0 += g_state[jj][(size_t)m * SD + p0];
                    v1 += g_state[jj][(size_t)m * SD + p0 + 1];
                }
                v0 *= 0.125f;
                v1 *= 0.125f;
                *(float2*)&g_hprev[(size_t)m * SD + p0] = make_float2(v0, v1);
                *(float2*)&g_hiddens[(size_t)t * BB * DD + (size_t)m * DD + p0]
                    = make_float2(v0, v1);
                uint32_t u1, u2;
                split2_pair(v0, v1, u1, u2);
                int qi = m * KQ + (p0 >> 1);
                g_abf[9][0][qi] = u1;
                g_abf[9][1][qi] = u2;
            }
            __syncthreads();
            if (tid == 0) g_tcnt[mh * 54 + tile] = 0;
        }
        __syncthreads();
    }
}

__global__ __launch_bounds__(256, 2)
void recur_persist(const float* __restrict__ hidden) {
    __shared__ float sm[2][32][33];
    __shared__ int s_old;
    const int bid = blockIdx.x;
    const int G = gridDim.x;
    const int tid = threadIdx.x;

    // initial prep (t = 0): hprev = hidden, plus splits
    for (int i = bid * 256 + tid; i < BB * 425; i += G * 256) {
        int m = i / 425;
        int qd = i - m * 425;
        int d0 = 2 * qd;
        float v0 = hidden[m * DD + d0];
        float v1 = hidden[m * DD + d0 + 1];
        *(float2*)&g_hprev[(size_t)m * SD + d0] = make_float2(v0, v1);
        uint32_t u1, u2;
        split2_pair(v0, v1, u1, u2);
        int qi = m * KQ + qd;
        g_abf[9][0][qi] = u1;
        g_abf[9][1][qi] = u2;
    }
    grid_sync();

    for (int t = 0; t < TT; ++t) {
        #pragma unroll
        for (int lvl = 0; lvl < 5; ++lvl) {
            const int jobs = c_nm[lvl] * 108;
            for (int j = bid; j < jobs; j += G)
                do_job(t, lvl, j, sm, &s_old);
            grid_sync();
        }
    }
}

// ---------------------------------------------------------------------------
// K5: mean over T, decoder, log_softmax, new_hidden.
// ---------------------------------------------------------------------------
__global__ void final_kernel(const float* __restrict__ masks,
                             const float* __restrict__ decW,
                             const float* __restrict__ decb,
                             float* __restrict__ out) {
    int b = blockIdx.x;
    int tid = threadIdx.x;
    __shared__ float sout[DD];
    __shared__ float lg[NCC];
    __shared__ float lse;

    float mask_last = masks[b * TT + TT - 1];
    for (int d = tid; d < DD; d += blockDim.x) {
        float ms = 0.f;
        #pragma unroll
        for (int j = 1; j <= 8; j++) ms += g_state[j][b * SD + d];
        ms *= 0.125f;
        float last_raw = ms * mask_last;
        float acc = last_raw;
        for (int t = 0; t < TT - 1; t++)
            acc += g_hiddens[(size_t)t * BB * DD + b * DD + d] * masks[b * TT + t];
        sout[d] = acc * (1.f / TT);
        out[NCC * BB + b * DD + d] = last_raw;
    }
    __syncthreads();

    for (int c = tid; c < NCC; c += blockDim.x) {
        float acc = decb[c];
        const float* w = decW + (size_t)c * DD;
        for (int d = 0; d < DD; d++) acc = fmaf(sout[d], w[d], acc);
        lg[c] = acc;
    }
    __syncthreads();

    if (tid == 0) {
        float mx = lg[0];
        for (int c = 1; c < NCC; c++) mx = fmaxf(mx, lg[c]);
        float s = 0.f;
        for (int c = 0; c < NCC; c++) s += expf(lg[c] - mx);
        lse = mx + logf(s);
    }
    __syncthreads();

    for (int c = tid; c < NCC; c += blockDim.x)
        out[b * NCC + c] = lg[c] - lse;
}

// ---------------------------------------------------------------------------
// Host launcher
// ---------------------------------------------------------------------------
extern "C" void kernel_launch(void* const* d_in, const int* in_sizes, int n_in,
                              void* d_out, int out_size) {
    const int*   tokens = (const int*)  d_in[0];
    const float* masks  = (const float*)d_in[1];
    const int*   pos    = (const int*)  d_in[2];
    const int*   ner    = (const int*)  d_in[3];
    const float* hidden = (const float*)d_in[4];
    const float* encW   = (const float*)d_in[5];
    const float* nerW   = (const float*)d_in[6];
    const float* posW   = (const float*)d_in[7];
    const float* aggW   = (const float*)d_in[8];
    const float* aggb   = (const float*)d_in[9];
    const float* W0     = (const float*)d_in[10];
    const float* Ws     = (const float*)d_in[11];
    const float* decW   = (const float*)d_in[12];
    const float* decb   = (const float*)d_in[13];
    float* out = (float*)d_out;

    static int s_grid = 0;
    if (s_grid == 0) {
        int dev = 0;
        cudaGetDevice(&dev);
        cudaDeviceProp prop;
        cudaGetDeviceProperties(&prop, dev);
        s_grid = prop.multiProcessorCount;   // 1 CTA/SM: co-resident, cheap barrier
    }

    float *p_combined, *p_x, *p_xw0;
    cudaGetSymbolAddress((void**)&p_combined, g_combined);
    cudaGetSymbolAddress((void**)&p_x,        g_x);
    cudaGetSymbolAddress((void**)&p_xw0,      g_xw0);

    // 1) gather embeddings + pack weights (independent)
    gather_kernel<<<TT * BB, 128>>>(tokens, ner, pos, encW, nerW, posW);
    pack_w<<<9 * NKT * NTILE, 128>>>(W0, Ws);

    // 2) agg linear: x = combined @ aggW^T + aggb   [8192, 850]
    {
        dim3 g((DD + 63) / 64, (TT * BB) / 64);
        gemm_tile<true, true><<<g, 256>>>(p_combined, aggW, aggb, p_x,
                                          TT * BB, DD, CIN, CIN, CIN, DD);
    }
    // 3) xw0 = x @ W0[0:DD, :]   [8192, 1700]
    {
        dim3 g((D2 + 63) / 64, (TT * BB) / 64);
        gemm_tile<false, false><<<g, 256>>>(p_x, W0, nullptr, p_xw0,
                                            TT * BB, D2, DD, DD, D2, D2);
    }

    // 4) whole recurrence in ONE persistent kernel
    recur_persist<<<s_grid, 256>>>(hidden);

    // 5) mean over T, decoder, log_softmax, new_hidden
    final_kernel<<<BB, 256>>>(masks, decW, decb, out);
}